// round 7
// baseline (speedup 1.0000x reference)
#include <cuda_runtime.h>
#include <cstdint>

// B=2048, D=3706, total=B*D=7,589,888 (divisible by 512)
// inputs: d_in[0] fake [B,D] f32; d_in[1] minb [D] f32; d_in[2] lens [D,4] f32
// output: dist f32 [B,D,6] then val f32 [B,D]
//
// b0=min[d]; b_{k+1}=b_k+relu(len[d,k])+1e-4 (strictly increasing)
// dist[r] = (r==0 || a>b[r-1]) && (r==5 || a<b[r]); a==b_k -> all zeros
// val = sum r*dist[r]
//
// R7: TPB=512; BOTH outputs staged in smem and flushed with TMA bulk stores
// (12KB dist + 2KB val per block, evict_first policy). Longer contiguous
// write runs per request for DRAM page locality; zero per-thread STGs.
// fake stays default-policy -> L2-resident across graph replays (R4 win).

#define EPSK 1e-4f
#define TPB 512

__global__ void __launch_bounds__(TPB)
discret_kernel(const float* __restrict__ fake,
               const float* __restrict__ minb,
               const float4* __restrict__ lens,
               float* __restrict__ out_dist,   // [B*D*6]
               float* __restrict__ out_val,    // [B*D]
               int total, int D)
{
    __shared__ __align__(16) float sdist[TPB * 6];   // 12 KB
    __shared__ __align__(16) float sval[TPB];        // 2 KB

    int t   = threadIdx.x;
    int idx = blockIdx.x * TPB + t;

    float d0 = 0.f, d1 = 0.f, d2 = 0.f, d3 = 0.f, d4 = 0.f, d5 = 0.f;
    float v  = 0.f;

    if (idx < total) {
        int d = idx % D;

        float a  = fake[idx];              // default policy: L2-resident across replays
        float4 L = __ldg(&lens[d]);
        float b0 = __ldg(&minb[d]);
        float b1 = b0 + fmaxf(L.x, 0.0f) + EPSK;
        float b2 = b1 + fmaxf(L.y, 0.0f) + EPSK;
        float b3 = b2 + fmaxf(L.z, 0.0f) + EPSK;
        float b4 = b3 + fmaxf(L.w, 0.0f) + EPSK;

        d0 = (a < b0)           ? 1.0f : 0.0f;
        d1 = (a > b0 && a < b1) ? 1.0f : 0.0f;
        d2 = (a > b1 && a < b2) ? 1.0f : 0.0f;
        d3 = (a > b2 && a < b3) ? 1.0f : 0.0f;
        d4 = (a > b3 && a < b4) ? 1.0f : 0.0f;
        d5 = (a > b4)           ? 1.0f : 0.0f;

        v = d1 + 2.0f * d2 + 3.0f * d3 + 4.0f * d4 + 5.0f * d5;
    }

    // stage into smem (stride-6 word writes: benign 2-way bank conflict)
    float* s = sdist + t * 6;
    s[0] = d0; s[1] = d1; s[2] = d2; s[3] = d3; s[4] = d4; s[5] = d5;
    sval[t] = v;
    __syncthreads();

    int block_first = blockIdx.x * TPB;
    int n_valid = total - block_first;

    if (n_valid >= TPB) {
        if (t == 0) {
            // order generic smem stores before async-proxy reads
            asm volatile("fence.proxy.async.shared::cta;" ::: "memory");

            uint32_t sa_d, sa_v;
            asm("{ .reg .u64 x; cvta.to.shared.u64 x, %1; cvt.u32.u64 %0, x; }"
                : "=r"(sa_d) : "l"(sdist));
            asm("{ .reg .u64 x; cvta.to.shared.u64 x, %1; cvt.u32.u64 %0, x; }"
                : "=r"(sa_v) : "l"(sval));
            uint64_t ga_d = (uint64_t)(out_dist + (size_t)block_first * 6);
            uint64_t ga_v = (uint64_t)(out_val + (size_t)block_first);

            asm volatile(
                "{\n\t"
                ".reg .b64 pol;\n\t"
                "createpolicy.fractional.L2::evict_first.b64 pol, 1.0;\n\t"
                "cp.async.bulk.global.shared::cta.bulk_group.L2::cache_hint "
                "[%0], [%1], %2, pol;\n\t"
                "cp.async.bulk.global.shared::cta.bulk_group.L2::cache_hint "
                "[%3], [%4], %5, pol;\n\t"
                "cp.async.bulk.commit_group;\n\t"
                "cp.async.bulk.wait_group.read 0;\n\t"
                "}"
                :: "l"(ga_d), "r"(sa_d), "n"(TPB * 6 * 4),
                   "l"(ga_v), "r"(sa_v), "n"(TPB * 4)
                : "memory");
        }
    } else {
        // tail block (unused for this shape, kept for generality)
        float* g = out_dist + (size_t)block_first * 6;
        for (int i = t; i < n_valid * 6; i += TPB)
            __stcs(&g[i], sdist[i]);
        for (int i = t; i < n_valid; i += TPB)
            __stcs(&out_val[block_first + i], sval[i]);
    }
}

extern "C" void kernel_launch(void* const* d_in, const int* in_sizes, int n_in,
                              void* d_out, int out_size)
{
    const float*  fake = (const float*)d_in[0];
    const float*  minb = (const float*)d_in[1];
    const float4* lens = (const float4*)d_in[2];

    int total = in_sizes[0];          // B*D
    int D     = in_sizes[1];          // 3706

    float* out  = (float*)d_out;
    float* dist = out;                          // [B*D*6]
    float* val  = out + (size_t)total * 6;      // [B*D]

    int blocks = (total + TPB - 1) / TPB;
    discret_kernel<<<blocks, TPB>>>(fake, minb, lens, dist, val, total, D);
}